// round 13
// baseline (speedup 1.0000x reference)
#include <cuda_runtime.h>
#include <cstdint>

// ---------------- problem constants ----------------
#define TT 512      // tokens
#define HH 2048     // hidden
#define EE 64       // experts
#define TOPK 8
#define II 768      // moe intermediate
#define CAP 192     // max tokens per expert

#define BK 16

// swiglu: CTA 64x96, 4 warps 1(m)x4(n), warp tile 64x24 dual-B
#define SW_LDA 20
#define SW_ASZ (64 * SW_LDA * 4)           // 5120 B
#define SW_LDB 104
#define SW_BSZ (BK * SW_LDB * 4)           // 6656 B
#define SW_STAGE (SW_ASZ + 2 * SW_BSZ)     // 18432 B
#define SW_SMEM (4 * SW_STAGE)             // 73728 B (4 buffers)

// down: CTA 64x256, 4 warps 1(m)x4(n), warp tile 64x64
#define DN_LDA 20
#define DN_ASZ (64 * DN_LDA * 4)           // 5120 B
#define DN_LDB 264
#define DN_BSZ (BK * DN_LDB * 4)           // 16896 B
#define DN_STAGE (DN_ASZ + DN_BSZ)         // 22016 B
#define DN_SMEM (4 * DN_STAGE)             // 88064 B (4 buffers)

// ---------------- device scratch (static; no allocation allowed) -------------
__device__ int   g_counts[EE];
__device__ int   g_tok[EE * CAP];
__device__ float g_wt[EE * CAP];
__device__ float g_xtf[(size_t)TT * HH];   // tf32-pre-rounded x (4 MB)
// swiglu activations: rows [0, EE*CAP) routed (slot-indexed), [EE*CAP, +TT) shared
__device__ float g_act[(size_t)(EE * CAP + TT) * II];

// ---------------- PTX helpers -------------------------------------------------
__device__ __forceinline__ uint32_t smem_u32(const void* p) {
    uint32_t a;
    asm("{ .reg .u64 t; cvta.to.shared.u64 t, %1; cvt.u32.u64 %0, t; }"
        : "=r"(a) : "l"(p));
    return a;
}
// round fp32 -> tf32 (round-to-nearest; removes the HMMA truncation bias)
__device__ __forceinline__ uint32_t tf32r(float f) {
    uint32_t u;
    asm("cvt.rna.tf32.f32 %0, %1;" : "=r"(u) : "f"(f));
    return u;
}
__device__ __forceinline__ void cp16(uint32_t dst, const float* src, int sz) {
    asm volatile("cp.async.cg.shared.global [%0], [%1], 16, %2;"
                 :: "r"(dst), "l"(src), "r"(sz) : "memory");
}
__device__ __forceinline__ void cp_commit() {
    asm volatile("cp.async.commit_group;" ::: "memory");
}
__device__ __forceinline__ void cp_wait2() {
    asm volatile("cp.async.wait_group 2;" ::: "memory");
}
__device__ __forceinline__ void mma8(float c[4], const uint32_t a[4], const uint32_t b[2]) {
    asm volatile(
        "mma.sync.aligned.m16n8k8.row.col.f32.tf32.tf32.f32 "
        "{%0,%1,%2,%3}, {%4,%5,%6,%7}, {%8,%9}, {%0,%1,%2,%3};"
        : "+f"(c[0]), "+f"(c[1]), "+f"(c[2]), "+f"(c[3])
        : "r"(a[0]), "r"(a[1]), "r"(a[2]), "r"(a[3]), "r"(b[0]), "r"(b[1]));
}
__device__ __forceinline__ float silu(float g) { return g / (1.f + __expf(-g)); }

// ============================================================================
// kernel 0: zero per-expert counts
// ============================================================================
__global__ void zero_counts_kernel() {
    if (threadIdx.x < EE) g_counts[threadIdx.x] = 0;
}

// ============================================================================
// kernel 0b: pre-round x into tf32 (A path becomes cvt-free everywhere)
// ============================================================================
__global__ void __launch_bounds__(256) round_x_kernel(const float* __restrict__ x) {
    int i = blockIdx.x * 256 + threadIdx.x;   // float4 index; grid covers TT*HH/4
    float4 v = ((const float4*)x)[i];
    uint4 o;
    o.x = tf32r(v.x); o.y = tf32r(v.y); o.z = tf32r(v.z); o.w = tf32r(v.w);
    ((uint4*)g_xtf)[i] = o;
}

// ============================================================================
// kernel 1: router, 4 tokens per block (uses RAW x: gate logits stay exact)
// ============================================================================
__global__ void __launch_bounds__(256) router_kernel(
    const float* __restrict__ x,
    const float* __restrict__ gate_w,
    const float* __restrict__ gate_b)
{
    __shared__ float xs[4][HH];
    __shared__ float score[4][EE];
    __shared__ float biased[4][EE];
    int t0 = blockIdx.x * 4;
    int tid = threadIdx.x;

    for (int i = tid; i < 4 * HH; i += 256)
        xs[i >> 11][i & (HH - 1)] = x[(size_t)t0 * HH + i];
    __syncthreads();

    int e = tid >> 2;
    int q = tid & 3;
    const float* gw = gate_w + (size_t)e * HH;
    float a0 = 0.f, a1 = 0.f, a2 = 0.f, a3 = 0.f;
    for (int h = q * (HH / 4); h < (q + 1) * (HH / 4); h += 4) {
        float4 g4 = *(const float4*)(gw + h);
        a0 += xs[0][h] * g4.x + xs[0][h+1] * g4.y + xs[0][h+2] * g4.z + xs[0][h+3] * g4.w;
        a1 += xs[1][h] * g4.x + xs[1][h+1] * g4.y + xs[1][h+2] * g4.z + xs[1][h+3] * g4.w;
        a2 += xs[2][h] * g4.x + xs[2][h+1] * g4.y + xs[2][h+2] * g4.z + xs[2][h+3] * g4.w;
        a3 += xs[3][h] * g4.x + xs[3][h+1] * g4.y + xs[3][h+2] * g4.z + xs[3][h+3] * g4.w;
    }
    a0 += __shfl_down_sync(~0u, a0, 2); a0 += __shfl_down_sync(~0u, a0, 1);
    a1 += __shfl_down_sync(~0u, a1, 2); a1 += __shfl_down_sync(~0u, a1, 1);
    a2 += __shfl_down_sync(~0u, a2, 2); a2 += __shfl_down_sync(~0u, a2, 1);
    a3 += __shfl_down_sync(~0u, a3, 2); a3 += __shfl_down_sync(~0u, a3, 1);
    if (q == 0) {
        float b = gate_b[e];
        float s0 = 1.f / (1.f + __expf(-a0));
        float s1 = 1.f / (1.f + __expf(-a1));
        float s2 = 1.f / (1.f + __expf(-a2));
        float s3 = 1.f / (1.f + __expf(-a3));
        score[0][e] = s0; biased[0][e] = s0 + b;
        score[1][e] = s1; biased[1][e] = s1 + b;
        score[2][e] = s2; biased[2][e] = s2 + b;
        score[3][e] = s3; biased[3][e] = s3 + b;
    }
    __syncthreads();

    if (tid < 4) {
        int t = t0 + tid;
        bool used[EE];
        #pragma unroll
        for (int i = 0; i < EE; i++) used[i] = false;
        int   idx[TOPK];
        float w[TOPK];
        float sum = 0.f;
        for (int k = 0; k < TOPK; k++) {
            float best = -1e30f; int bi = 0;
            for (int ee = 0; ee < EE; ee++)
                if (!used[ee] && biased[tid][ee] > best) { best = biased[tid][ee]; bi = ee; }
            used[bi] = true; idx[k] = bi; w[k] = score[tid][bi]; sum += w[k];
        }
        float inv = 1.f / (sum + 1e-20f);
        for (int k = 0; k < TOPK; k++) {
            int ee = idx[k];
            int slot = atomicAdd(&g_counts[ee], 1);
            if (slot < CAP) {
                g_tok[ee * CAP + slot] = t;
                g_wt[ee * CAP + slot]  = w[k] * inv;
            }
        }
    }
}

// ============================================================================
// kernel 2: SwiGLU dual-B GEMM. CTA 64x96, 4 warps (1x4), warp tile 64x24.
//   8 n-tiles -> 576 CTAs -> balanced 2-wave schedule (was 1.46 waves).
//   1.83 issue slots per MMA. cp.async 4-buffer / 3-deep pipeline.
//   A from g_xtf (tf32, no cvt); B (weights) cvt.rna after LDS.
// ============================================================================
__global__ void __launch_bounds__(128, 2) swiglu_kernel(
    const float* __restrict__ w_gate, const float* __restrict__ w_up,
    const float* __restrict__ sw_gate, const float* __restrict__ sw_up)
{
    extern __shared__ char sm[];
    int e = blockIdx.z;
    bool se = (e == EE);
    int cnt;
    const float *Wg, *Wu;
    if (se) { cnt = TT; Wg = sw_gate; Wu = sw_up; }
    else {
        cnt = min(g_counts[e], CAP);
        Wg = w_gate + (size_t)e * HH * II;
        Wu = w_up   + (size_t)e * HH * II;
    }
    int m0 = blockIdx.y * 64;
    if (m0 >= cnt) return;
    int n0 = blockIdx.x * 96;

    int tid  = threadIdx.x;
    int lane = tid & 31;
    int wn   = tid >> 5;                 // warp = n-tile index 0..3
    int qg = lane >> 2, qt = lane & 3;

    uint32_t smb = smem_u32(sm);

    // producer A: row = tid>>1 (0..63), two float4 slots at (tid&1)*2 + {0,1}
    int ar    = tid >> 1;
    int aslot = (tid & 1) * 2;
    int gm    = m0 + ar;
    int av    = (gm < cnt) ? 16 : 0;
    const float* aptr = g_xtf;
    if (av) {
        int tok = se ? gm : g_tok[e * CAP + gm];
        aptr = g_xtf + (size_t)tok * HH + aslot * 4;
    }
    uint32_t asts0 = (uint32_t)(ar * (SW_LDA * 4) + aslot * 16);
    uint32_t asts1 = asts0 + 16;

    // producer B: row = tid>>3 (0..15), col4 = (tid&7) + 8j, j in 0..2 (per matrix)
    int br = tid >> 3;
    int bq = tid & 7;
    const float* gptr = Wg + (size_t)br * II + n0 + bq * 4;
    const float* uptr = Wu + (size_t)br * II + n0 + bq * 4;
    uint32_t bsts = (uint32_t)(br * (SW_LDB * 4) + bq * 16);

    const int NC = HH / BK;              // 128 chunks

    auto prefetch = [&](int c) {
        uint32_t st = smb + (uint32_t)(c & 3) * SW_STAGE;
        size_t ko = (size_t)c * BK;
        cp16(st + asts0, aptr + ko, av);
        cp16(st + asts1, aptr + ko + 4, av);
        uint32_t bg = st + SW_ASZ, bu = bg + SW_BSZ;
        const float* g = gptr + ko * II;
        const float* u = uptr + ko * II;
        #pragma unroll
        for (int j = 0; j < 3; j++) {
            cp16(bg + bsts + j * 128, g + 32 * j, 16);
            cp16(bu + bsts + j * 128, u + 32 * j, 16);
        }
    };

    float cg[4][3][4], cu[4][3][4];
    #pragma unroll
    for (int mi = 0; mi < 4; mi++)
        #pragma unroll
        for (int ni = 0; ni < 3; ni++)
            #pragma unroll
            for (int r = 0; r < 4; r++) { cg[mi][ni][r] = 0.f; cu[mi][ni][r] = 0.f; }

    prefetch(0); cp_commit();
    prefetch(1); cp_commit();
    prefetch(2); cp_commit();

    for (int c = 0; c < NC; c++) {
        cp_wait2();
        __syncthreads();
        if (c + 3 < NC) prefetch(c + 3);
        cp_commit();   // empty group keeps wait_group accounting

        const uint32_t* As = (const uint32_t*)(sm + (size_t)(c & 3) * SW_STAGE);
        const float*    Bg = (const float*)(As + SW_ASZ / 4);
        const float*    Bu = Bg + SW_BSZ / 4;

        #pragma unroll
        for (int kk = 0; kk < 2; kk++) {
            int kb = kk * 8;
            uint32_t a[4][4];
            #pragma unroll
            for (int mi = 0; mi < 4; mi++) {
                int r = mi * 16 + qg;
                a[mi][0] = As[r * SW_LDA + kb + qt];
                a[mi][1] = As[(r + 8) * SW_LDA + kb + qt];
                a[mi][2] = As[r * SW_LDA + kb + qt + 4];
                a[mi][3] = As[(r + 8) * SW_LDA + kb + qt + 4];
            }
            uint32_t bgf[3][2], buf2[3][2];
            #pragma unroll
            for (int ni = 0; ni < 3; ni++) {
                int cc = wn * 24 + ni * 8 + qg;
                bgf[ni][0]  = tf32r(Bg[(kb + qt) * SW_LDB + cc]);
                bgf[ni][1]  = tf32r(Bg[(kb + qt + 4) * SW_LDB + cc]);
                buf2[ni][0] = tf32r(Bu[(kb + qt) * SW_LDB + cc]);
                buf2[ni][1] = tf32r(Bu[(kb + qt + 4) * SW_LDB + cc]);
            }
            #pragma unroll
            for (int mi = 0; mi < 4; mi++)
                #pragma unroll
                for (int ni = 0; ni < 3; ni++) {
                    mma8(cg[mi][ni], a[mi], bgf[ni]);
                    mma8(cu[mi][ni], a[mi], buf2[ni]);
                }
        }
    }

    // ---- epilogue: act = tf32(silu(g) * u) -> g_act (pre-rounded for down) ----
    size_t Rbase = se ? (size_t)EE * CAP : (size_t)e * CAP;
    #pragma unroll
    for (int mi = 0; mi < 4; mi++) {
        #pragma unroll
        for (int ni = 0; ni < 3; ni++) {
            int col = n0 + wn * 24 + ni * 8 + qt * 2;
            #pragma unroll
            for (int h = 0; h < 2; h++) {
                int m = m0 + mi * 16 + qg + 8 * h;
                if (m < cnt) {
                    float gv0 = cg[mi][ni][2 * h], gv1 = cg[mi][ni][2 * h + 1];
                    float uv0 = cu[mi][ni][2 * h], uv1 = cu[mi][ni][2 * h + 1];
                    float2 o;
                    o.x = __uint_as_float(tf32r(silu(gv0) * uv0));
                    o.y = __uint_as_float(tf32r(silu(gv1) * uv1));
                    *(float2*)(g_act + (Rbase + m) * II + col) = o;
                }
            }
        }
    }
}

// ============================================================================
// kernel 3: down-projection. CTA 64x256, 4 warps (1x4), warp tile 64x64.
//   2.5 issue slots per MMA. cp.async 4-buffer / 3-deep pipeline.
//   A (g_act) tf32 pre-rounded (no cvt); B cvt.rna after LDS.
//   out pre-zeroed; routed and shared both atomicAdd.
// ============================================================================
__global__ void __launch_bounds__(128, 2) down_kernel(
    const float* __restrict__ w_down,
    const float* __restrict__ sw_down,
    float* __restrict__ out)
{
    extern __shared__ char sm[];
    int e = blockIdx.z;
    bool se = (e == EE);
    int cnt;
    const float* Wd;
    size_t Rbase;
    if (se) { cnt = TT; Wd = sw_down; Rbase = (size_t)EE * CAP; }
    else {
        cnt = min(g_counts[e], CAP);
        Wd = w_down + (size_t)e * II * HH;
        Rbase = (size_t)e * CAP;
    }
    int m0 = blockIdx.y * 64;
    if (m0 >= cnt) return;
    int n0 = blockIdx.x * 256;

    int tid  = threadIdx.x;
    int lane = tid & 31;
    int wn   = tid >> 5;                 // warp = n-tile index 0..3
    int qg = lane >> 2, qt = lane & 3;

    uint32_t smb = smem_u32(sm);

    // producer A: row = tid>>1 (0..63), two float4 slots at (tid&1)*2 + {0,1}
    int ar    = tid >> 1;
    int aslot = (tid & 1) * 2;
    int av    = (m0 + ar < cnt) ? 16 : 0;
    const float* aptr = g_act + (Rbase + m0 + ar) * II + aslot * 4;  // in-bounds even when invalid
    uint32_t asts0 = (uint32_t)(ar * (DN_LDA * 4) + aslot * 16);
    uint32_t asts1 = asts0 + 16;

    // producer B: row = tid>>3 (0..15), col4 = (tid&7) + 8j, j in 0..7
    int br = tid >> 3;
    int bq = tid & 7;
    const float* bptr = Wd + (size_t)br * HH + n0 + bq * 4;
    uint32_t bsts = (uint32_t)(br * (DN_LDB * 4) + bq * 16);

    const int NC = II / BK;              // 48 chunks

    auto prefetch = [&](int c) {
        uint32_t st = smb + (uint32_t)(c & 3) * DN_STAGE;
        size_t ko = (size_t)c * BK;
        cp16(st + asts0, aptr + ko, av);
        cp16(st + asts1, aptr + ko + 4, av);
        uint32_t bb = st + DN_ASZ;
        const float* b = bptr + ko * HH;
        #pragma unroll
        for (int j = 0; j < 8; j++)
            cp16(bb + bsts + j * 128, b + 32 * j, 16);
    };

    float cc[4][8][4];
    #pragma unroll
    for (int mi = 0; mi < 4; mi++)
        #pragma unroll
        for (int ni = 0; ni < 8; ni++)
            #pragma unroll
            for (int r = 0; r < 4; r++) cc[mi][ni][r] = 0.f;

    prefetch(0); cp_commit();
    prefetch(1); cp_commit();
    prefetch(2); cp_commit();

    for (int c = 0; c < NC; c++) {
        cp_wait2();
        __syncthreads();
        if (c + 3 < NC) prefetch(c + 3);
        cp_commit();

        const uint32_t* As = (const uint32_t*)(sm + (size_t)(c & 3) * DN_STAGE);
        const float*    Bs = (const float*)(As + DN_ASZ / 4);

        #pragma unroll
        for (int kk = 0; kk < 2; kk++) {
            int kb = kk * 8;
            uint32_t a[4][4];
            #pragma unroll
            for (int mi = 0; mi < 4; mi++) {
                int r = mi * 16 + qg;
                a[mi][0] = As[r * DN_LDA + kb + qt];
                a[mi][1] = As[(r + 8) * DN_LDA + kb + qt];
                a[mi][2] = As[r * DN_LDA + kb + qt + 4];
                a[mi][3] = As[(r + 8) * DN_LDA + kb + qt + 4];
            }
            uint32_t b[8][2];
            #pragma unroll
            for (int ni = 0; ni < 8; ni++) {
                int col = wn * 64 + ni * 8 + qg;
                b[ni][0] = tf32r(Bs[(kb + qt) * DN_LDB + col]);
                b[ni][1] = tf32r(Bs[(kb + qt + 4) * DN_LDB + col]);
            }
            #pragma unroll
            for (int mi = 0; mi < 4; mi++)
                #pragma unroll
                for (int ni = 0; ni < 8; ni++)
                    mma8(cc[mi][ni], a[mi], b[ni]);
        }
    }

    // ---- epilogue: out[tok] += wt * C ----
    #pragma unroll
    for (int mi = 0; mi < 4; mi++) {
        #pragma unroll
        for (int h = 0; h < 2; h++) {
            int m = m0 + mi * 16 + qg + 8 * h;
            if (m >= cnt) continue;
            int tok;
            float wt = 1.f;
            if (se) { tok = m; }
            else    { tok = g_tok[e * CAP + m]; wt = g_wt[e * CAP + m]; }
            float* dst = out + (size_t)tok * HH;
            #pragma unroll
            for (int ni = 0; ni < 8; ni++) {
                int col = n0 + wn * 64 + ni * 8 + qt * 2;
                atomicAdd(dst + col,     cc[mi][ni][2 * h] * wt);
                atomicAdd(dst + col + 1, cc[mi][ni][2 * h + 1] * wt);
            }
        }
    }
}

// ============================================================================
// launch
// ============================================================================
extern "C" void kernel_launch(void* const* d_in, const int* in_sizes, int n_in,
                              void* d_out, int out_size)
{
    const float* x       = (const float*)d_in[0];
    const float* gate_w  = (const float*)d_in[1];
    const float* gate_b  = (const float*)d_in[2];
    const float* w_gate  = (const float*)d_in[3];
    const float* w_up    = (const float*)d_in[4];
    const float* w_down  = (const float*)d_in[5];
    const float* sw_gate = (const float*)d_in[6];
    const float* sw_up   = (const float*)d_in[7];
    const float* sw_down = (const float*)d_in[8];
    float* out = (float*)d_out;

    // host-side, non-stream API: idempotent, executes immediately (capture-safe)
    cudaFuncSetAttribute(swiglu_kernel, cudaFuncAttributeMaxDynamicSharedMemorySize, SW_SMEM);
    cudaFuncSetAttribute(down_kernel,   cudaFuncAttributeMaxDynamicSharedMemorySize, DN_SMEM);

    zero_counts_kernel<<<1, 64>>>();
    cudaMemsetAsync(out, 0, sizeof(float) * (size_t)TT * HH);
    round_x_kernel<<<(TT * HH / 4) / 256, 256>>>(x);
    router_kernel<<<TT / 4, 256>>>(x, gate_w, gate_b);

    // routed experts (z<64) + shared expert (z==64)
    swiglu_kernel<<<dim3(II / 96, TT / 64, EE + 1), 128, SW_SMEM>>>(
        w_gate, w_up, sw_gate, sw_up);
    down_kernel<<<dim3(HH / 256, TT / 64, EE + 1), 128, DN_SMEM>>>(
        w_down, sw_down, out);
}

// round 15
// speedup vs baseline: 1.6176x; 1.6176x over previous
#include <cuda_runtime.h>
#include <cstdint>

// ---------------- problem constants ----------------
#define TT 512      // tokens
#define HH 2048     // hidden
#define EE 64       // experts
#define TOPK 8
#define II 768      // moe intermediate
#define CAP 192     // max tokens per expert

#define BK 16

// swiglu: CTA 64x128, 4 warps 1(m)x4(n), warp tile 64x32 dual-B  (R12 proven)
#define SW_LDA 20
#define SW_ASZ (64 * SW_LDA * 4)           // 5120 B
#define SW_LDB 136
#define SW_BSZ (BK * SW_LDB * 4)           // 8704 B
#define SW_STAGE (SW_ASZ + 2 * SW_BSZ)     // 22528 B
#define SW_SMEM (4 * SW_STAGE)             // 90112 B (4 buffers)

// down: CTA 64x128, 4 warps 1(m)x4(n), warp tile 64x32, 3 CTAs/SM
#define DN_LDA 20
#define DN_ASZ (64 * DN_LDA * 4)           // 5120 B
#define DN_LDB 136
#define DN_BSZ (BK * DN_LDB * 4)           // 8704 B
#define DN_STAGE (DN_ASZ + DN_BSZ)         // 13824 B
#define DN_SMEM (4 * DN_STAGE)             // 55296 B (4 buffers)

// ---------------- device scratch (static; no allocation allowed) -------------
__device__ int   g_counts[EE];
__device__ int   g_tok[EE * CAP];
__device__ float g_wt[EE * CAP];
__device__ float g_xtf[(size_t)TT * HH];   // tf32-pre-rounded x (4 MB)
// swiglu activations: rows [0, EE*CAP) routed (slot-indexed), [EE*CAP, +TT) shared
__device__ float g_act[(size_t)(EE * CAP + TT) * II];

// ---------------- PTX helpers -------------------------------------------------
__device__ __forceinline__ uint32_t smem_u32(const void* p) {
    uint32_t a;
    asm("{ .reg .u64 t; cvta.to.shared.u64 t, %1; cvt.u32.u64 %0, t; }"
        : "=r"(a) : "l"(p));
    return a;
}
// round fp32 -> tf32 (round-to-nearest; removes the HMMA truncation bias)
__device__ __forceinline__ uint32_t tf32r(float f) {
    uint32_t u;
    asm("cvt.rna.tf32.f32 %0, %1;" : "=r"(u) : "f"(f));
    return u;
}
__device__ __forceinline__ void cp16(uint32_t dst, const float* src, int sz) {
    asm volatile("cp.async.cg.shared.global [%0], [%1], 16, %2;"
                 :: "r"(dst), "l"(src), "r"(sz) : "memory");
}
__device__ __forceinline__ void cp_commit() {
    asm volatile("cp.async.commit_group;" ::: "memory");
}
__device__ __forceinline__ void cp_wait2() {
    asm volatile("cp.async.wait_group 2;" ::: "memory");
}
__device__ __forceinline__ void mma8(float c[4], const uint32_t a[4], const uint32_t b[2]) {
    asm volatile(
        "mma.sync.aligned.m16n8k8.row.col.f32.tf32.tf32.f32 "
        "{%0,%1,%2,%3}, {%4,%5,%6,%7}, {%8,%9}, {%0,%1,%2,%3};"
        : "+f"(c[0]), "+f"(c[1]), "+f"(c[2]), "+f"(c[3])
        : "r"(a[0]), "r"(a[1]), "r"(a[2]), "r"(a[3]), "r"(b[0]), "r"(b[1]));
}
__device__ __forceinline__ float silu(float g) { return g / (1.f + __expf(-g)); }

// ============================================================================
// kernel 0: zero per-expert counts
// ============================================================================
__global__ void zero_counts_kernel() {
    if (threadIdx.x < EE) g_counts[threadIdx.x] = 0;
}

// ============================================================================
// kernel 0b: pre-round x into tf32 (A path becomes cvt-free everywhere)
// ============================================================================
__global__ void __launch_bounds__(256) round_x_kernel(const float* __restrict__ x) {
    int i = blockIdx.x * 256 + threadIdx.x;   // float4 index; grid covers TT*HH/4
    float4 v = ((const float4*)x)[i];
    uint4 o;
    o.x = tf32r(v.x); o.y = tf32r(v.y); o.z = tf32r(v.z); o.w = tf32r(v.w);
    ((uint4*)g_xtf)[i] = o;
}

// ============================================================================
// kernel 1: router, 4 tokens per block (uses RAW x: gate logits stay exact)
// ============================================================================
__global__ void __launch_bounds__(256) router_kernel(
    const float* __restrict__ x,
    const float* __restrict__ gate_w,
    const float* __restrict__ gate_b)
{
    __shared__ float xs[4][HH];
    __shared__ float score[4][EE];
    __shared__ float biased[4][EE];
    int t0 = blockIdx.x * 4;
    int tid = threadIdx.x;

    for (int i = tid; i < 4 * HH; i += 256)
        xs[i >> 11][i & (HH - 1)] = x[(size_t)t0 * HH + i];
    __syncthreads();

    int e = tid >> 2;
    int q = tid & 3;
    const float* gw = gate_w + (size_t)e * HH;
    float a0 = 0.f, a1 = 0.f, a2 = 0.f, a3 = 0.f;
    for (int h = q * (HH / 4); h < (q + 1) * (HH / 4); h += 4) {
        float4 g4 = *(const float4*)(gw + h);
        a0 += xs[0][h] * g4.x + xs[0][h+1] * g4.y + xs[0][h+2] * g4.z + xs[0][h+3] * g4.w;
        a1 += xs[1][h] * g4.x + xs[1][h+1] * g4.y + xs[1][h+2] * g4.z + xs[1][h+3] * g4.w;
        a2 += xs[2][h] * g4.x + xs[2][h+1] * g4.y + xs[2][h+2] * g4.z + xs[2][h+3] * g4.w;
        a3 += xs[3][h] * g4.x + xs[3][h+1] * g4.y + xs[3][h+2] * g4.z + xs[3][h+3] * g4.w;
    }
    a0 += __shfl_down_sync(~0u, a0, 2); a0 += __shfl_down_sync(~0u, a0, 1);
    a1 += __shfl_down_sync(~0u, a1, 2); a1 += __shfl_down_sync(~0u, a1, 1);
    a2 += __shfl_down_sync(~0u, a2, 2); a2 += __shfl_down_sync(~0u, a2, 1);
    a3 += __shfl_down_sync(~0u, a3, 2); a3 += __shfl_down_sync(~0u, a3, 1);
    if (q == 0) {
        float b = gate_b[e];
        float s0 = 1.f / (1.f + __expf(-a0));
        float s1 = 1.f / (1.f + __expf(-a1));
        float s2 = 1.f / (1.f + __expf(-a2));
        float s3 = 1.f / (1.f + __expf(-a3));
        score[0][e] = s0; biased[0][e] = s0 + b;
        score[1][e] = s1; biased[1][e] = s1 + b;
        score[2][e] = s2; biased[2][e] = s2 + b;
        score[3][e] = s3; biased[3][e] = s3 + b;
    }
    __syncthreads();

    if (tid < 4) {
        int t = t0 + tid;
        bool used[EE];
        #pragma unroll
        for (int i = 0; i < EE; i++) used[i] = false;
        int   idx[TOPK];
        float w[TOPK];
        float sum = 0.f;
        for (int k = 0; k < TOPK; k++) {
            float best = -1e30f; int bi = 0;
            for (int ee = 0; ee < EE; ee++)
                if (!used[ee] && biased[tid][ee] > best) { best = biased[tid][ee]; bi = ee; }
            used[bi] = true; idx[k] = bi; w[k] = score[tid][bi]; sum += w[k];
        }
        float inv = 1.f / (sum + 1e-20f);
        for (int k = 0; k < TOPK; k++) {
            int ee = idx[k];
            int slot = atomicAdd(&g_counts[ee], 1);
            if (slot < CAP) {
                g_tok[ee * CAP + slot] = t;
                g_wt[ee * CAP + slot]  = w[k] * inv;
            }
        }
    }
}

// ============================================================================
// kernel 2: SwiGLU dual-B GEMM. CTA 64x128, 4 warps (1x4), warp tile 64x32.
//   2.5 issue slots per MMA. cp.async 4-buffer / 3-deep pipeline.
//   A from g_xtf (tf32, no cvt); B (weights) cvt.rna after LDS.  (R12 proven)
// ============================================================================
__global__ void __launch_bounds__(128, 2) swiglu_kernel(
    const float* __restrict__ w_gate, const float* __restrict__ w_up,
    const float* __restrict__ sw_gate, const float* __restrict__ sw_up)
{
    extern __shared__ char sm[];
    int e = blockIdx.z;
    bool se = (e == EE);
    int cnt;
    const float *Wg, *Wu;
    if (se) { cnt = TT; Wg = sw_gate; Wu = sw_up; }
    else {
        cnt = min(g_counts[e], CAP);
        Wg = w_gate + (size_t)e * HH * II;
        Wu = w_up   + (size_t)e * HH * II;
    }
    int m0 = blockIdx.y * 64;
    if (m0 >= cnt) return;
    int n0 = blockIdx.x * 128;

    int tid  = threadIdx.x;
    int lane = tid & 31;
    int wn   = tid >> 5;                 // warp = n-tile index 0..3
    int qg = lane >> 2, qt = lane & 3;

    uint32_t smb = smem_u32(sm);

    // producer A: row = tid>>1 (0..63), two float4 slots at (tid&1)*2 + {0,1}
    int ar    = tid >> 1;
    int aslot = (tid & 1) * 2;
    int gm    = m0 + ar;
    int av    = (gm < cnt) ? 16 : 0;
    const float* aptr = g_xtf;
    if (av) {
        int tok = se ? gm : g_tok[e * CAP + gm];
        aptr = g_xtf + (size_t)tok * HH + aslot * 4;
    }
    uint32_t asts0 = (uint32_t)(ar * (SW_LDA * 4) + aslot * 16);
    uint32_t asts1 = asts0 + 16;

    // producer B: row = tid>>3 (0..15), col4 = (tid&7) + 8j, j in 0..3 (per matrix)
    int br = tid >> 3;
    int bq = tid & 7;
    const float* gptr = Wg + (size_t)br * II + n0 + bq * 4;
    const float* uptr = Wu + (size_t)br * II + n0 + bq * 4;
    uint32_t bsts = (uint32_t)(br * (SW_LDB * 4) + bq * 16);

    const int NC = HH / BK;              // 128 chunks

    auto prefetch = [&](int c) {
        uint32_t st = smb + (uint32_t)(c & 3) * SW_STAGE;
        size_t ko = (size_t)c * BK;
        cp16(st + asts0, aptr + ko, av);
        cp16(st + asts1, aptr + ko + 4, av);
        uint32_t bg = st + SW_ASZ, bu = bg + SW_BSZ;
        const float* g = gptr + ko * II;
        const float* u = uptr + ko * II;
        #pragma unroll
        for (int j = 0; j < 4; j++) {
            cp16(bg + bsts + j * 128, g + 32 * j, 16);
            cp16(bu + bsts + j * 128, u + 32 * j, 16);
        }
    };

    float cg[4][4][4], cu[4][4][4];
    #pragma unroll
    for (int mi = 0; mi < 4; mi++)
        #pragma unroll
        for (int ni = 0; ni < 4; ni++)
            #pragma unroll
            for (int r = 0; r < 4; r++) { cg[mi][ni][r] = 0.f; cu[mi][ni][r] = 0.f; }

    prefetch(0); cp_commit();
    prefetch(1); cp_commit();
    prefetch(2); cp_commit();

    for (int c = 0; c < NC; c++) {
        cp_wait2();
        __syncthreads();
        if (c + 3 < NC) prefetch(c + 3);
        cp_commit();   // empty group keeps wait_group accounting

        const uint32_t* As = (const uint32_t*)(sm + (size_t)(c & 3) * SW_STAGE);
        const float*    Bg = (const float*)(As + SW_ASZ / 4);
        const float*    Bu = Bg + SW_BSZ / 4;

        #pragma unroll
        for (int kk = 0; kk < 2; kk++) {
            int kb = kk * 8;
            uint32_t a[4][4];
            #pragma unroll
            for (int mi = 0; mi < 4; mi++) {
                int r = mi * 16 + qg;
                a[mi][0] = As[r * SW_LDA + kb + qt];
                a[mi][1] = As[(r + 8) * SW_LDA + kb + qt];
                a[mi][2] = As[r * SW_LDA + kb + qt + 4];
                a[mi][3] = As[(r + 8) * SW_LDA + kb + qt + 4];
            }
            uint32_t bgf[4][2], buf2[4][2];
            #pragma unroll
            for (int ni = 0; ni < 4; ni++) {
                int cc = wn * 32 + ni * 8 + qg;
                bgf[ni][0]  = tf32r(Bg[(kb + qt) * SW_LDB + cc]);
                bgf[ni][1]  = tf32r(Bg[(kb + qt + 4) * SW_LDB + cc]);
                buf2[ni][0] = tf32r(Bu[(kb + qt) * SW_LDB + cc]);
                buf2[ni][1] = tf32r(Bu[(kb + qt + 4) * SW_LDB + cc]);
            }
            #pragma unroll
            for (int mi = 0; mi < 4; mi++)
                #pragma unroll
                for (int ni = 0; ni < 4; ni++) {
                    mma8(cg[mi][ni], a[mi], bgf[ni]);
                    mma8(cu[mi][ni], a[mi], buf2[ni]);
                }
        }
    }

    // ---- epilogue: act = tf32(silu(g) * u) -> g_act (pre-rounded for down) ----
    size_t Rbase = se ? (size_t)EE * CAP : (size_t)e * CAP;
    #pragma unroll
    for (int mi = 0; mi < 4; mi++) {
        #pragma unroll
        for (int ni = 0; ni < 4; ni++) {
            int col = n0 + wn * 32 + ni * 8 + qt * 2;
            #pragma unroll
            for (int h = 0; h < 2; h++) {
                int m = m0 + mi * 16 + qg + 8 * h;
                if (m < cnt) {
                    float gv0 = cg[mi][ni][2 * h], gv1 = cg[mi][ni][2 * h + 1];
                    float uv0 = cu[mi][ni][2 * h], uv1 = cu[mi][ni][2 * h + 1];
                    float2 o;
                    o.x = __uint_as_float(tf32r(silu(gv0) * uv0));
                    o.y = __uint_as_float(tf32r(silu(gv1) * uv1));
                    *(float2*)(g_act + (Rbase + m) * II + col) = o;
                }
            }
        }
    }
}

// ============================================================================
// kernel 3: down-projection. CTA 64x128, 4 warps (1x4), warp tile 64x32.
//   3 CTAs/SM (12 warps) for latency hiding. cp.async 4-buffer / 3-deep.
//   A (g_act) tf32 pre-rounded (no cvt); B cvt.rna after LDS.
//   out pre-zeroed; routed and shared both atomicAdd.
// ============================================================================
__global__ void __launch_bounds__(128, 3) down_kernel(
    const float* __restrict__ w_down,
    const float* __restrict__ sw_down,
    float* __restrict__ out)
{
    extern __shared__ char sm[];
    int e = blockIdx.z;
    bool se = (e == EE);
    int cnt;
    const float* Wd;
    size_t Rbase;
    if (se) { cnt = TT; Wd = sw_down; Rbase = (size_t)EE * CAP; }
    else {
        cnt = min(g_counts[e], CAP);
        Wd = w_down + (size_t)e * II * HH;
        Rbase = (size_t)e * CAP;
    }
    int m0 = blockIdx.y * 64;
    if (m0 >= cnt) return;
    int n0 = blockIdx.x * 128;

    int tid  = threadIdx.x;
    int lane = tid & 31;
    int wn   = tid >> 5;                 // warp = n-tile index 0..3
    int qg = lane >> 2, qt = lane & 3;

    uint32_t smb = smem_u32(sm);

    // producer A: row = tid>>1 (0..63), two float4 slots at (tid&1)*2 + {0,1}
    int ar    = tid >> 1;
    int aslot = (tid & 1) * 2;
    int av    = (m0 + ar < cnt) ? 16 : 0;
    const float* aptr = g_act + (Rbase + m0 + ar) * II + aslot * 4;  // in-bounds even when invalid
    uint32_t asts0 = (uint32_t)(ar * (DN_LDA * 4) + aslot * 16);
    uint32_t asts1 = asts0 + 16;

    // producer B: row = tid>>3 (0..15), col4 = (tid&7) + 8j, j in 0..3
    int br = tid >> 3;
    int bq = tid & 7;
    const float* bptr = Wd + (size_t)br * HH + n0 + bq * 4;
    uint32_t bsts = (uint32_t)(br * (DN_LDB * 4) + bq * 16);

    const int NC = II / BK;              // 48 chunks

    auto prefetch = [&](int c) {
        uint32_t st = smb + (uint32_t)(c & 3) * DN_STAGE;
        size_t ko = (size_t)c * BK;
        cp16(st + asts0, aptr + ko, av);
        cp16(st + asts1, aptr + ko + 4, av);
        uint32_t bb = st + DN_ASZ;
        const float* b = bptr + ko * HH;
        #pragma unroll
        for (int j = 0; j < 4; j++)
            cp16(bb + bsts + j * 128, b + 32 * j, 16);
    };

    float cc[4][4][4];
    #pragma unroll
    for (int mi = 0; mi < 4; mi++)
        #pragma unroll
        for (int ni = 0; ni < 4; ni++)
            #pragma unroll
            for (int r = 0; r < 4; r++) cc[mi][ni][r] = 0.f;

    prefetch(0); cp_commit();
    prefetch(1); cp_commit();
    prefetch(2); cp_commit();

    for (int c = 0; c < NC; c++) {
        cp_wait2();
        __syncthreads();
        if (c + 3 < NC) prefetch(c + 3);
        cp_commit();

        const uint32_t* As = (const uint32_t*)(sm + (size_t)(c & 3) * DN_STAGE);
        const float*    Bs = (const float*)(As + DN_ASZ / 4);

        #pragma unroll
        for (int kk = 0; kk < 2; kk++) {
            int kb = kk * 8;
            uint32_t a[4][4];
            #pragma unroll
            for (int mi = 0; mi < 4; mi++) {
                int r = mi * 16 + qg;
                a[mi][0] = As[r * DN_LDA + kb + qt];
                a[mi][1] = As[(r + 8) * DN_LDA + kb + qt];
                a[mi][2] = As[r * DN_LDA + kb + qt + 4];
                a[mi][3] = As[(r + 8) * DN_LDA + kb + qt + 4];
            }
            uint32_t b[4][2];
            #pragma unroll
            for (int ni = 0; ni < 4; ni++) {
                int col = wn * 32 + ni * 8 + qg;
                b[ni][0] = tf32r(Bs[(kb + qt) * DN_LDB + col]);
                b[ni][1] = tf32r(Bs[(kb + qt + 4) * DN_LDB + col]);
            }
            #pragma unroll
            for (int mi = 0; mi < 4; mi++)
                #pragma unroll
                for (int ni = 0; ni < 4; ni++)
                    mma8(cc[mi][ni], a[mi], b[ni]);
        }
    }

    // ---- epilogue: out[tok] += wt * C ----
    #pragma unroll
    for (int mi = 0; mi < 4; mi++) {
        #pragma unroll
        for (int h = 0; h < 2; h++) {
            int m = m0 + mi * 16 + qg + 8 * h;
            if (m >= cnt) continue;
            int tok;
            float wt = 1.f;
            if (se) { tok = m; }
            else    { tok = g_tok[e * CAP + m]; wt = g_wt[e * CAP + m]; }
            float* dst = out + (size_t)tok * HH;
            #pragma unroll
            for (int ni = 0; ni < 4; ni++) {
                int col = n0 + wn * 32 + ni * 8 + qt * 2;
                atomicAdd(dst + col,     cc[mi][ni][2 * h] * wt);
                atomicAdd(dst + col + 1, cc[mi][ni][2 * h + 1] * wt);
            }
        }
    }
}

// ============================================================================
// launch
// ============================================================================
extern "C" void kernel_launch(void* const* d_in, const int* in_sizes, int n_in,
                              void* d_out, int out_size)
{
    const float* x       = (const float*)d_in[0];
    const float* gate_w  = (const float*)d_in[1];
    const float* gate_b  = (const float*)d_in[2];
    const float* w_gate  = (const float*)d_in[3];
    const float* w_up    = (const float*)d_in[4];
    const float* w_down  = (const float*)d_in[5];
    const float* sw_gate = (const float*)d_in[6];
    const float* sw_up   = (const float*)d_in[7];
    const float* sw_down = (const float*)d_in[8];
    float* out = (float*)d_out;

    // host-side, non-stream API: idempotent, executes immediately (capture-safe)
    cudaFuncSetAttribute(swiglu_kernel, cudaFuncAttributeMaxDynamicSharedMemorySize, SW_SMEM);
    cudaFuncSetAttribute(down_kernel,   cudaFuncAttributeMaxDynamicSharedMemorySize, DN_SMEM);

    zero_counts_kernel<<<1, 64>>>();
    cudaMemsetAsync(out, 0, sizeof(float) * (size_t)TT * HH);
    round_x_kernel<<<(TT * HH / 4) / 256, 256>>>(x);
    router_kernel<<<TT / 4, 256>>>(x, gate_w, gate_b);

    // routed experts (z<64) + shared expert (z==64)
    swiglu_kernel<<<dim3(II / 128, TT / 64, EE + 1), 128, SW_SMEM>>>(
        w_gate, w_up, sw_gate, sw_up);
    down_kernel<<<dim3(HH / 128, TT / 64, EE + 1), 128, DN_SMEM>>>(
        w_down, sw_down, out);
}